// round 1
// baseline (speedup 1.0000x reference)
#include <cuda_runtime.h>

// Problem constants (fixed by reference setup_inputs)
#define BROWS 16384
#define DCOLS 512
#define D4    (DCOLS / 4)          // 128 float4 per row
#define WARPS_PER_BLOCK 16
#define THREADS_PER_BLOCK (WARPS_PER_BLOCK * 32)
#define NBLOCKS (BROWS / WARPS_PER_BLOCK)   // 1024
#define INV_T 10.0f                 // 1 / TEMPERATURE

// Scratch for deterministic two-pass reduction (no cudaMalloc allowed)
__device__ float g_partial[NBLOCKS];

__global__ __launch_bounds__(THREADS_PER_BLOCK)
void contrastive_rows_kernel(const float4* __restrict__ shared_i,
                             const float4* __restrict__ specific_i,
                             const float4* __restrict__ shared_j,
                             const float4* __restrict__ specific_j) {
    const int warp = threadIdx.x >> 5;
    const int lane = threadIdx.x & 31;
    const int row  = blockIdx.x * WARPS_PER_BLOCK + warp;

    const size_t rowbase = (size_t)row * D4;

    float s_ss = 0.f, s_sp = 0.f, s_ps = 0.f, s_pp = 0.f;

    // 512 floats per row = 128 float4; 32 lanes -> 4 iterations.
    // Fully coalesced: each warp reads 512 contiguous bytes per array per iter.
    #pragma unroll
    for (int it = 0; it < D4 / 32; ++it) {
        const size_t idx = rowbase + it * 32 + lane;
        const float4 a = __ldg(&shared_i[idx]);    // shared_i row
        const float4 b = __ldg(&specific_i[idx]);  // specific_i row
        const float4 c = __ldg(&shared_j[idx]);    // shared_j row
        const float4 d = __ldg(&specific_j[idx]);  // specific_j row

        s_ss = fmaf(a.x, c.x, s_ss); s_ss = fmaf(a.y, c.y, s_ss);
        s_ss = fmaf(a.z, c.z, s_ss); s_ss = fmaf(a.w, c.w, s_ss);

        s_sp = fmaf(a.x, d.x, s_sp); s_sp = fmaf(a.y, d.y, s_sp);
        s_sp = fmaf(a.z, d.z, s_sp); s_sp = fmaf(a.w, d.w, s_sp);

        s_ps = fmaf(b.x, c.x, s_ps); s_ps = fmaf(b.y, c.y, s_ps);
        s_ps = fmaf(b.z, c.z, s_ps); s_ps = fmaf(b.w, c.w, s_ps);

        s_pp = fmaf(b.x, d.x, s_pp); s_pp = fmaf(b.y, d.y, s_pp);
        s_pp = fmaf(b.z, d.z, s_pp); s_pp = fmaf(b.w, d.w, s_pp);
    }

    // Warp-level reduction of the 4 dot products
    #pragma unroll
    for (int off = 16; off > 0; off >>= 1) {
        s_ss += __shfl_down_sync(0xffffffffu, s_ss, off);
        s_sp += __shfl_down_sync(0xffffffffu, s_sp, off);
        s_ps += __shfl_down_sync(0xffffffffu, s_ps, off);
        s_pp += __shfl_down_sync(0xffffffffu, s_pp, off);
    }

    __shared__ float sh_row[WARPS_PER_BLOCK];
    if (lane == 0) {
        const float l0 = s_ss * INV_T;
        const float l1 = s_sp * INV_T;
        const float l2 = s_ps * INV_T;
        const float l3 = s_pp * INV_T;
        const float m  = fmaxf(fmaxf(l0, l1), fmaxf(l2, l3));
        const float lse = m + logf(expf(l0 - m) + expf(l1 - m) +
                                   expf(l2 - m) + expf(l3 - m));
        // per-row loss contribution: -(log_softmax[0]) = lse - l0
        sh_row[warp] = lse - l0;
    }
    __syncthreads();

    if (threadIdx.x == 0) {
        float s = 0.f;
        #pragma unroll
        for (int i = 0; i < WARPS_PER_BLOCK; ++i) s += sh_row[i];
        g_partial[blockIdx.x] = s;
    }
}

__global__ __launch_bounds__(1024)
void final_reduce_kernel(float* __restrict__ out) {
    __shared__ float sh[32];
    const int tid  = threadIdx.x;
    const int lane = tid & 31;
    const int warp = tid >> 5;

    float v = g_partial[tid];   // NBLOCKS == 1024 == blockDim.x

    #pragma unroll
    for (int off = 16; off > 0; off >>= 1)
        v += __shfl_down_sync(0xffffffffu, v, off);

    if (lane == 0) sh[warp] = v;
    __syncthreads();

    if (warp == 0) {
        float w = (lane < 32) ? sh[lane] : 0.f;
        #pragma unroll
        for (int off = 16; off > 0; off >>= 1)
            w += __shfl_down_sync(0xffffffffu, w, off);
        if (lane == 0) out[0] = w / (float)BROWS;
    }
}

extern "C" void kernel_launch(void* const* d_in, const int* in_sizes, int n_in,
                              void* d_out, int out_size) {
    const float4* shared_i   = (const float4*)d_in[0];
    const float4* specific_i = (const float4*)d_in[1];
    const float4* shared_j   = (const float4*)d_in[2];
    const float4* specific_j = (const float4*)d_in[3];
    float* out = (float*)d_out;

    contrastive_rows_kernel<<<NBLOCKS, THREADS_PER_BLOCK>>>(
        shared_i, specific_i, shared_j, specific_j);
    final_reduce_kernel<<<1, 1024>>>(out);
}